// round 4
// baseline (speedup 1.0000x reference)
#include <cuda_runtime.h>
#include <stdint.h>

#define BB 2
#define SS 2048
#define HH 8
#define DHV 64

__device__ float g_qp[BB * SS * 512];
__device__ float g_kp[BB * SS * 512];
__device__ float g_vp[BB * SS * 512];
__device__ float g_ctx[BB * SS * 512];

// ---------------------------------------------------------------------------
// helpers
// ---------------------------------------------------------------------------
// hi = bf16x2(x0 lower, x1 upper); lo = bf16x2 of residuals
__device__ __forceinline__ void split2(float x0, float x1, uint32_t& hi, uint32_t& lo) {
    asm("cvt.rn.bf16x2.f32 %0, %1, %2;" : "=r"(hi) : "f"(x1), "f"(x0));
    float h0 = __uint_as_float(hi << 16);          // bf16->f32 exact
    float h1 = __uint_as_float(hi & 0xffff0000u);
    asm("cvt.rn.bf16x2.f32 %0, %1, %2;" : "=r"(lo) : "f"(x1 - h1), "f"(x0 - h0));
}

__device__ __forceinline__ void mma_bf16(float c[4], const uint32_t a[4],
                                         const uint32_t b[2]) {
    asm volatile(
        "mma.sync.aligned.m16n8k16.row.col.f32.bf16.bf16.f32 "
        "{%0,%1,%2,%3}, {%4,%5,%6,%7}, {%8,%9}, {%0,%1,%2,%3};"
        : "+f"(c[0]), "+f"(c[1]), "+f"(c[2]), "+f"(c[3])
        : "r"(a[0]), "r"(a[1]), "r"(a[2]), "r"(a[3]), "r"(b[0]), "r"(b[1]));
}

__device__ __forceinline__ uint32_t sptr(const void* p) {
    return (uint32_t)__cvta_generic_to_shared(p);
}
__device__ __forceinline__ void ldsm4(uint32_t r[4], uint32_t a) {
    asm volatile("ldmatrix.sync.aligned.m8n8.x4.shared.b16 {%0,%1,%2,%3}, [%4];"
                 : "=r"(r[0]), "=r"(r[1]), "=r"(r[2]), "=r"(r[3]) : "r"(a));
}
__device__ __forceinline__ void ldsm4t(uint32_t r[4], uint32_t a) {
    asm volatile("ldmatrix.sync.aligned.m8n8.x4.trans.shared.b16 {%0,%1,%2,%3}, [%4];"
                 : "=r"(r[0]), "=r"(r[1]), "=r"(r[2]), "=r"(r[3]) : "r"(a));
}

// ---------------------------------------------------------------------------
// bf16x2-split GEMM: C[4096,512] = A[4096,512] @ W[512,512] + bias
// 128x128x32 block tile, 8 warps (2x4), warp tile 64x32.
// A: hi/lo planes packed along k (2 halves/word), ldmatrix (row-major).
// W: hi/lo planes packed along n, ldmatrix.trans (row-major [k][n]).
// ---------------------------------------------------------------------------
#define GSTA 20   // A-plane row stride in words (16 data + 4 pad)
#define GSTB 68   // B-plane row stride in words (64 data + 4 pad)

__device__ __forceinline__ void gemm_body(const float* __restrict__ A,
                                          const float* __restrict__ W,
                                          const float* __restrict__ bias,
                                          float* __restrict__ C) {
    __shared__ uint32_t sAh[128 * GSTA], sAl[128 * GSTA];
    __shared__ uint32_t sBh[32 * GSTB], sBl[32 * GSTB];

    const int tid = threadIdx.x, lane = tid & 31, warp = tid >> 5;
    const int g = lane >> 2, tg = lane & 3;
    const int wr = warp >> 2, wc = warp & 3;
    const int brow = blockIdx.x * 128, bcol = blockIdx.y * 128;
    const int lm = lane >> 3, lr = lane & 7;
    // A-frag (row-major): rows m, k halves
    const int a_row = lr + (lm & 1) * 8, a_kh = (lm >> 1) * 8;
    // B-frag via trans from [k][n]: k rows, n halves
    const int b_krow = (lm & 1) * 8 + lr, b_nh = 8 * (lm >> 1);

    const uint32_t sAh_b = sptr(sAh), sAl_b = sptr(sAl);
    const uint32_t sBh_b = sptr(sBh), sBl_b = sptr(sBl);

    float acc[4][4][4];
#pragma unroll
    for (int mt = 0; mt < 4; mt++)
#pragma unroll
        for (int nt = 0; nt < 4; nt++)
#pragma unroll
            for (int e = 0; e < 4; e++) acc[mt][nt][e] = 0.f;

    for (int kt = 0; kt < 16; kt++) {   // k-tile = 32 floats
        // A fill: 128 rows x 32 floats -> 16 words/row/plane
#pragma unroll
        for (int i = 0; i < 4; i++) {
            int idx = tid + i * 256;
            int row = idx >> 3, c4 = (idx & 7) * 4;
            float4 a = *(const float4*)&A[(size_t)(brow + row) * 512 + kt * 32 + c4];
            uint32_t h0, l0, h1, l1;
            split2(a.x, a.y, h0, l0);
            split2(a.z, a.w, h1, l1);
            int w = row * GSTA + (c4 >> 1);
            sAh[w] = h0; sAh[w + 1] = h1;
            sAl[w] = l0; sAl[w + 1] = l1;
        }
        // B fill: 32 k-rows x 128 n-floats -> 64 words/row/plane
#pragma unroll
        for (int i = 0; i < 4; i++) {
            int idx = tid + i * 256;
            int row = idx >> 5, c4 = (idx & 31) * 4;
            float4 b = *(const float4*)&W[(size_t)(kt * 32 + row) * 512 + bcol + c4];
            uint32_t h0, l0, h1, l1;
            split2(b.x, b.y, h0, l0);
            split2(b.z, b.w, h1, l1);
            int w = row * GSTB + (c4 >> 1);
            sBh[w] = h0; sBh[w + 1] = h1;
            sBl[w] = l0; sBl[w + 1] = l1;
        }
        __syncthreads();

#pragma unroll
        for (int s = 0; s < 2; s++) {   // two k16 steps
            uint32_t ah[4][4], al[4][4];
#pragma unroll
            for (int mt = 0; mt < 4; mt++) {
                uint32_t off = (uint32_t)((wr * 64 + mt * 16 + a_row) * (GSTA * 2) +
                                          s * 16 + a_kh) * 2;
                ldsm4(ah[mt], sAh_b + off);
                ldsm4(al[mt], sAl_b + off);
            }
#pragma unroll
            for (int np = 0; np < 2; np++) {   // each covers two n8 tiles
                uint32_t bh[4], bl[4];
                uint32_t off = (uint32_t)((s * 16 + b_krow) * (GSTB * 2) +
                                          wc * 32 + np * 16 + b_nh) * 2;
                ldsm4t(bh, sBh_b + off);
                ldsm4t(bl, sBl_b + off);
#pragma unroll
                for (int mt = 0; mt < 4; mt++) {
                    mma_bf16(acc[mt][2 * np],     ah[mt], &bh[0]);
                    mma_bf16(acc[mt][2 * np],     ah[mt], &bl[0]);
                    mma_bf16(acc[mt][2 * np],     al[mt], &bh[0]);
                    mma_bf16(acc[mt][2 * np + 1], ah[mt], &bh[2]);
                    mma_bf16(acc[mt][2 * np + 1], ah[mt], &bl[2]);
                    mma_bf16(acc[mt][2 * np + 1], al[mt], &bh[2]);
                }
            }
        }
        __syncthreads();
    }

#pragma unroll
    for (int mt = 0; mt < 4; mt++) {
        const int r0 = brow + wr * 64 + mt * 16 + g;
#pragma unroll
        for (int nt = 0; nt < 4; nt++) {
            const int c = bcol + wc * 32 + nt * 8 + 2 * tg;
            float2 b2 = *(const float2*)&bias[c];
            *(float2*)&C[(size_t)r0 * 512 + c] =
                make_float2(acc[mt][nt][0] + b2.x, acc[mt][nt][1] + b2.y);
            *(float2*)&C[(size_t)(r0 + 8) * 512 + c] =
                make_float2(acc[mt][nt][2] + b2.x, acc[mt][nt][3] + b2.y);
        }
    }
}

__global__ __launch_bounds__(256) void proj_kernel(
    const float* __restrict__ q, const float* __restrict__ k, const float* __restrict__ v,
    const float* __restrict__ Wq, const float* __restrict__ bq,
    const float* __restrict__ Wk, const float* __restrict__ bk,
    const float* __restrict__ Wv, const float* __restrict__ bv) {
    const int z = blockIdx.z;
    const float* A = (z == 0) ? q : (z == 1) ? k : v;
    const float* W = (z == 0) ? Wq : (z == 1) ? Wk : Wv;
    const float* bias = (z == 0) ? bq : (z == 1) ? bk : bv;
    float* C = (z == 0) ? g_qp : (z == 1) ? g_kp : g_vp;
    gemm_body(A, W, bias, C);
}

__global__ __launch_bounds__(256) void out_gemm_kernel(
    const float* __restrict__ Wo, const float* __restrict__ bo, float* __restrict__ out) {
    gemm_body(g_ctx, Wo, bo, out);
}

// ---------------------------------------------------------------------------
// Flash attention: bf16x2-split mmas, register-resident P, ldmatrix frags.
// 128 q-rows/block, 4 warps x 32 rows; KV tiles of 64. Head slab contiguous
// (raw reshape). /sqrt(64) post-softmax folded into epilogue; head concat
// folded into the ctx store address.
// ---------------------------------------------------------------------------
#define AST 36   // row stride in words (32 data + 4 pad)

__global__ __launch_bounds__(128, 2) void attn_kernel() {
    extern __shared__ uint32_t smw[];
    uint32_t* sQh = smw;                 // 128*AST
    uint32_t* sQl = sQh + 128 * AST;
    uint32_t* sKh = sQl + 128 * AST;     // 64*AST each below
    uint32_t* sKl = sKh + 64 * AST;
    uint32_t* sVh = sKl + 64 * AST;
    uint32_t* sVl = sVh + 64 * AST;

    const int b = blockIdx.z, h = blockIdx.y;
    const int q0 = blockIdx.x * 128;
    const size_t slab = ((size_t)b * HH + h) * SS * DHV;
    const float* Qh_ = g_qp + slab;
    const float* Kh_ = g_kp + slab;
    const float* Vh_ = g_vp + slab;

    const int tid = threadIdx.x, lane = tid & 31, warp = tid >> 5;
    const int g = lane >> 2, tg = lane & 3;
    const int lm = lane >> 3, lr = lane & 7;
    const int a_row = lr + (lm & 1) * 8, a_kh = (lm >> 1) * 8;   // Q (row-major A)
    const int k_nrow = 8 * (lm >> 1) + lr, k_kh = (lm & 1) * 8;  // K ([n][k] B)
    const int v_krow = (lm & 1) * 8 + lr, v_nh = 8 * (lm >> 1);  // V (trans B)

    const uint32_t sQh_b = sptr(sQh), sQl_b = sptr(sQl);
    const uint32_t sKh_b = sptr(sKh), sKl_b = sptr(sKl);
    const uint32_t sVh_b = sptr(sVh), sVl_b = sptr(sVl);

    // Q fill: 128 x 64 floats -> 32 words/row/plane
#pragma unroll
    for (int i = 0; i < 16; i++) {
        int idx = tid + i * 128;
        int row = idx >> 4, c4 = (idx & 15) * 4;
        float4 a = *(const float4*)&Qh_[(size_t)(q0 + row) * DHV + c4];
        uint32_t h0, l0, h1, l1;
        split2(a.x, a.y, h0, l0);
        split2(a.z, a.w, h1, l1);
        int w = row * AST + (c4 >> 1);
        sQh[w] = h0; sQh[w + 1] = h1;
        sQl[w] = l0; sQl[w + 1] = l1;
    }

    float m[2][2], l[2][2], o[2][8][4];
#pragma unroll
    for (int mt = 0; mt < 2; mt++) {
        m[mt][0] = m[mt][1] = -1e30f;
        l[mt][0] = l[mt][1] = 0.f;
#pragma unroll
        for (int nt = 0; nt < 8; nt++)
#pragma unroll
            for (int e = 0; e < 4; e++) o[mt][nt][e] = 0.f;
    }

    for (int t = 0; t < SS; t += 64) {
        __syncthreads();
        // K,V fill: 64 x 64 floats each
#pragma unroll
        for (int i = 0; i < 8; i++) {
            int idx = tid + i * 128;
            int row = idx >> 4, c4 = (idx & 15) * 4;
            int w = row * AST + (c4 >> 1);
            float4 kv = *(const float4*)&Kh_[(size_t)(t + row) * DHV + c4];
            uint32_t h0, l0, h1, l1;
            split2(kv.x, kv.y, h0, l0);
            split2(kv.z, kv.w, h1, l1);
            sKh[w] = h0; sKh[w + 1] = h1;
            sKl[w] = l0; sKl[w + 1] = l1;
            float4 vv = *(const float4*)&Vh_[(size_t)(t + row) * DHV + c4];
            split2(vv.x, vv.y, h0, l0);
            split2(vv.z, vv.w, h1, l1);
            sVh[w] = h0; sVh[w + 1] = h1;
            sVl[w] = l0; sVl[w + 1] = l1;
        }
        __syncthreads();

        // --- S = Q @ K^T ---
        float s[2][8][4];
#pragma unroll
        for (int mt = 0; mt < 2; mt++)
#pragma unroll
            for (int nt = 0; nt < 8; nt++)
#pragma unroll
                for (int e = 0; e < 4; e++) s[mt][nt][e] = 0.f;

#pragma unroll
        for (int ks = 0; ks < 4; ks++) {   // d in k16 steps
            uint32_t qh[2][4], ql[2][4];
#pragma unroll
            for (int mt = 0; mt < 2; mt++) {
                uint32_t off = (uint32_t)((warp * 32 + mt * 16 + a_row) * (AST * 2) +
                                          ks * 16 + a_kh) * 2;
                ldsm4(qh[mt], sQh_b + off);
                ldsm4(ql[mt], sQl_b + off);
            }
#pragma unroll
            for (int np = 0; np < 4; np++) {   // kv in n16 chunks
                uint32_t kh[4], kl[4];
                uint32_t off = (uint32_t)((np * 16 + k_nrow) * (AST * 2) +
                                          ks * 16 + k_kh) * 2;
                ldsm4(kh, sKh_b + off);
                ldsm4(kl, sKl_b + off);
#pragma unroll
                for (int mt = 0; mt < 2; mt++) {
                    mma_bf16(s[mt][2 * np],     qh[mt], &kh[0]);
                    mma_bf16(s[mt][2 * np],     qh[mt], &kl[0]);
                    mma_bf16(s[mt][2 * np],     ql[mt], &kh[0]);
                    mma_bf16(s[mt][2 * np + 1], qh[mt], &kh[2]);
                    mma_bf16(s[mt][2 * np + 1], qh[mt], &kl[2]);
                    mma_bf16(s[mt][2 * np + 1], ql[mt], &kh[2]);
                }
            }
        }

        // --- online softmax (rows g, g+8 per m16 tile; split over quad) ---
#pragma unroll
        for (int mt = 0; mt < 2; mt++) {
            float mx0 = -1e30f, mx1 = -1e30f;
#pragma unroll
            for (int nt = 0; nt < 8; nt++) {
                mx0 = fmaxf(mx0, fmaxf(s[mt][nt][0], s[mt][nt][1]));
                mx1 = fmaxf(mx1, fmaxf(s[mt][nt][2], s[mt][nt][3]));
            }
            mx0 = fmaxf(mx0, __shfl_xor_sync(~0u, mx0, 1));
            mx0 = fmaxf(mx0, __shfl_xor_sync(~0u, mx0, 2));
            mx1 = fmaxf(mx1, __shfl_xor_sync(~0u, mx1, 1));
            mx1 = fmaxf(mx1, __shfl_xor_sync(~0u, mx1, 2));
            const float mn0 = fmaxf(m[mt][0], mx0);
            const float mn1 = fmaxf(m[mt][1], mx1);
            const float al0 = __expf(m[mt][0] - mn0);
            const float al1 = __expf(m[mt][1] - mn1);
            m[mt][0] = mn0; m[mt][1] = mn1;
            float s0 = 0.f, s1 = 0.f;
#pragma unroll
            for (int nt = 0; nt < 8; nt++) {
                s[mt][nt][0] = __expf(s[mt][nt][0] - mn0);
                s[mt][nt][1] = __expf(s[mt][nt][1] - mn0);
                s[mt][nt][2] = __expf(s[mt][nt][2] - mn1);
                s[mt][nt][3] = __expf(s[mt][nt][3] - mn1);
                s0 += s[mt][nt][0] + s[mt][nt][1];
                s1 += s[mt][nt][2] + s[mt][nt][3];
            }
            s0 += __shfl_xor_sync(~0u, s0, 1);
            s0 += __shfl_xor_sync(~0u, s0, 2);
            s1 += __shfl_xor_sync(~0u, s1, 1);
            s1 += __shfl_xor_sync(~0u, s1, 2);
            l[mt][0] = l[mt][0] * al0 + s0;
            l[mt][1] = l[mt][1] * al1 + s1;
#pragma unroll
            for (int nt = 0; nt < 8; nt++) {
                o[mt][nt][0] *= al0; o[mt][nt][1] *= al0;
                o[mt][nt][2] *= al1; o[mt][nt][3] *= al1;
            }
        }

        // --- O += P @ V ; P direct from registers (C-frag -> A-frag) ---
#pragma unroll
        for (int ks = 0; ks < 4; ks++) {   // kv in k16 steps
            uint32_t ph[2][4], pl[2][4];
#pragma unroll
            for (int mt = 0; mt < 2; mt++) {
                split2(s[mt][2 * ks][0],     s[mt][2 * ks][1],     ph[mt][0], pl[mt][0]);
                split2(s[mt][2 * ks][2],     s[mt][2 * ks][3],     ph[mt][1], pl[mt][1]);
                split2(s[mt][2 * ks + 1][0], s[mt][2 * ks + 1][1], ph[mt][2], pl[mt][2]);
                split2(s[mt][2 * ks + 1][2], s[mt][2 * ks + 1][3], ph[mt][3], pl[mt][3]);
            }
#pragma unroll
            for (int np = 0; np < 4; np++) {   // d in n16 chunks
                uint32_t vh[4], vl[4];
                uint32_t off = (uint32_t)((ks * 16 + v_krow) * (AST * 2) +
                                          np * 16 + v_nh) * 2;
                ldsm4t(vh, sVh_b + off);
                ldsm4t(vl, sVl_b + off);
#pragma unroll
                for (int mt = 0; mt < 2; mt++) {
                    mma_bf16(o[mt][2 * np],     ph[mt], &vh[0]);
                    mma_bf16(o[mt][2 * np],     ph[mt], &vl[0]);
                    mma_bf16(o[mt][2 * np],     pl[mt], &vh[0]);
                    mma_bf16(o[mt][2 * np + 1], ph[mt], &vh[2]);
                    mma_bf16(o[mt][2 * np + 1], ph[mt], &vl[2]);
                    mma_bf16(o[mt][2 * np + 1], pl[mt], &vh[2]);
                }
            }
        }
    }

    // epilogue: ctx[b][s][h*64+d] = O / (l * 8)
#pragma unroll
    for (int mt = 0; mt < 2; mt++) {
        const float inv0 = 1.0f / (l[mt][0] * 8.0f);
        const float inv1 = 1.0f / (l[mt][1] * 8.0f);
        const int row0 = q0 + warp * 32 + mt * 16 + g;
#pragma unroll
        for (int nt = 0; nt < 8; nt++) {
            const int col = h * DHV + nt * 8 + 2 * tg;
            *(float2*)&g_ctx[((size_t)b * SS + row0) * 512 + col] =
                make_float2(o[mt][nt][0] * inv0, o[mt][nt][1] * inv0);
            *(float2*)&g_ctx[((size_t)b * SS + row0 + 8) * 512 + col] =
                make_float2(o[mt][nt][2] * inv1, o[mt][nt][3] * inv1);
        }
    }
}

// ---------------------------------------------------------------------------
extern "C" void kernel_launch(void* const* d_in, const int* in_sizes, int n_in,
                              void* d_out, int out_size) {
    (void)in_sizes; (void)n_in; (void)out_size;
    const float* q  = (const float*)d_in[0];
    const float* k  = (const float*)d_in[1];
    const float* v  = (const float*)d_in[2];
    const float* Wq = (const float*)d_in[3];
    const float* bq = (const float*)d_in[4];
    const float* Wk = (const float*)d_in[5];
    const float* bk = (const float*)d_in[6];
    const float* Wv = (const float*)d_in[7];
    const float* bv = (const float*)d_in[8];
    const float* Wo = (const float*)d_in[9];
    const float* bo = (const float*)d_in[10];
    float* out = (float*)d_out;

    proj_kernel<<<dim3(32, 4, 3), 256>>>(q, k, v, Wq, bq, Wk, bk, Wv, bv);

    const int smem = (128 + 64 + 64) * AST * 2 * (int)sizeof(uint32_t);
    cudaFuncSetAttribute(attn_kernel, cudaFuncAttributeMaxDynamicSharedMemorySize, smem);
    attn_kernel<<<dim3(16, HH, BB), 128, smem>>>();

    out_gemm_kernel<<<dim3(32, 4, 1), 256>>>(Wo, bo, out);
}